// round 15
// baseline (speedup 1.0000x reference)
#include <cuda_runtime.h>
#include <cuda_fp16.h>
#include <stdint.h>
#include <math.h>

#define BATCH 4
#define SEQ 2048
#define DIM 1024
#define MTOT (BATCH*SEQ)
#define NITER 5
#define PADK 40
#define ARRB (128*PADK*2)
#define STGB (4*ARRB)
#define SMEMTOT (3*STGB)
#define MAXNZ 256
#define RPB 8
#define UTH 512
#define UPD_SMEM ((2*SEQ*4 + RPB*SEQ) * 4)   // gT0+gT1 (64KB) + s (64KB)

typedef uint16_t u16;
typedef uint32_t u32;

__device__ u16 g_xh[MTOT*DIM], g_xm[MTOT*DIM];
__device__ u16 g_WQTh[DIM*DIM], g_WQTm[DIM*DIM];
__device__ u16 g_WKTh[DIM*DIM], g_WKTm[DIM*DIM];
__device__ u16 g_W2Th[DIM*DIM], g_W2Tm[DIM*DIM];
__device__ u16 g_KWh[MTOT*DIM], g_KWm[MTOT*DIM];
__device__ float g_G[BATCH*SEQ*SEQ];
__device__ int   g_cnt[2][MTOT];
__device__ uint2 g_lst[2][MTOT*MAXNZ];   // entry-major: [p*MTOT+row] = {idx, w bits}

__device__ __forceinline__ u32 smem_u32(const void* p) {
    u32 a;
    asm("{ .reg .u64 t; cvta.to.shared.u64 t, %1; cvt.u32.u64 %0, t; }" : "=r"(a) : "l"(p));
    return a;
}
__device__ __forceinline__ void cpa16(u32 s, const void* g) {
    asm volatile("cp.async.cg.shared.global [%0], [%1], 16;" :: "r"(s), "l"(g) : "memory");
}
__device__ __forceinline__ void mmah(float* c, const u32* a, const u32* b) {
    asm volatile("mma.sync.aligned.m16n8k16.row.col.f32.f16.f16.f32 "
        "{%0,%1,%2,%3}, {%4,%5,%6,%7}, {%8,%9}, {%0,%1,%2,%3};"
        : "+f"(c[0]), "+f"(c[1]), "+f"(c[2]), "+f"(c[3])
        : "r"(a[0]), "r"(a[1]), "r"(a[2]), "r"(a[3]), "r"(b[0]), "r"(b[1]));
}
__device__ __forceinline__ void ldsm4(u32* r, u32 a) {
    asm volatile("ldmatrix.sync.aligned.m8n8.x4.shared.b16 {%0,%1,%2,%3}, [%4];"
        : "=r"(r[0]), "=r"(r[1]), "=r"(r[2]), "=r"(r[3]) : "r"(a));
}
__device__ __forceinline__ void ldsm2(u32* r, u32 a) {
    asm volatile("ldmatrix.sync.aligned.m8n8.x2.shared.b16 {%0,%1}, [%2];"
        : "=r"(r[0]), "=r"(r[1]) : "r"(a));
}
__device__ __forceinline__ void split2(float v, u16& h, u16& m) {
    __half hh = __float2half_rn(v);
    float r = v - __half2float(hh);
    __half mm = __float2half_rn(r);
    h = __half_as_ushort(hh); m = __half_as_ushort(mm);
}
__device__ __forceinline__ u32 pk(u16 a, u16 b) { return (u32)a | ((u32)b << 16); }

// C[M,N] = A[M,K]*B[N,K]^T, fp16 2-term, 3 passes, dual accumulators.
template <int SPLIT>
__global__ __launch_bounds__(256, 1)
void gemm_h2(const u16* __restrict__ Ah, const u16* __restrict__ Am,
             const u16* __restrict__ Bh, const u16* __restrict__ Bm,
             float* __restrict__ C, u16* __restrict__ Ch, u16* __restrict__ Cm,
             int Ktot, int ldc, long long sA, long long sB, long long sC)
{
    extern __shared__ char smc[];
    const u32 sb = smem_u32(smc);
    const int tid = threadIdx.x, wid = tid >> 5, lane = tid & 31;
    const int lr = lane >> 2, lq = lane & 3;
    const int mBase = blockIdx.y * 128, nBase = blockIdx.x * 128, z = blockIdx.z;
    const int warpM = (wid >> 2) * 64, warpN = (wid & 3) * 32;
    const int nst = Ktot >> 5;
    const long long aOff = (long long)z * sA, bOff = (long long)z * sB;

    const int l15 = lane & 15;
    const u32 aoff = ((u32)(warpM + l15) * PADK + (lane >> 4) * 8) * 2;
    const u32 boff = ((u32)(warpN + (l15 & 7)) * PADK + ((l15 >> 3) & 1) * 8) * 2;

    float accH[4][4][4], accC[4][4][4];
    #pragma unroll
    for (int i = 0; i < 4; i++)
        #pragma unroll
        for (int j = 0; j < 4; j++)
            #pragma unroll
            for (int r = 0; r < 4; r++) { accH[i][j][r] = 0.f; accC[i][j][r] = 0.f; }

    const u16* gp[4] = {Ah, Am, Bh, Bm};

    auto load_stage = [&](int s) {
        const u32 st = sb + (s % 3) * STGB;
        const int k0 = s << 5;
        #pragma unroll
        for (int a = 0; a < 4; a++) {
            const long long ro = (a < 2) ? aOff : bOff;
            const int rb = (a < 2) ? mBase : nBase;
            #pragma unroll
            for (int i = 0; i < 2; i++) {
                const int u = i * 256 + tid;
                const int r = u >> 2, kc = (u & 3) * 8;
                cpa16(st + a * ARRB + (r * PADK + kc) * 2,
                      gp[a] + ro + (long long)(rb + r) * Ktot + k0 + kc);
            }
        }
        asm volatile("cp.async.commit_group;" ::: "memory");
    };

    load_stage(0);
    if (nst > 1) load_stage(1);

    for (int s = 0; s < nst; s++) {
        asm volatile("cp.async.wait_group 1;" ::: "memory");
        __syncthreads();
        if (s + 2 < nst) load_stage(s + 2);

        const u32 stB = sb + (s % 3) * STGB;

        #pragma unroll
        for (int kk = 0; kk < 2; kk++) {
            u32 af[2][4][4], bf[2][4][2];
            #pragma unroll
            for (int sl = 0; sl < 2; sl++) {
                const u32 ab = stB + sl * ARRB + aoff + kk * 32;
                const u32 bb = stB + (2 + sl) * ARRB + boff + kk * 32;
                #pragma unroll
                for (int mt = 0; mt < 4; mt++) ldsm4(af[sl][mt], ab + mt * (16 * PADK * 2));
                #pragma unroll
                for (int nt = 0; nt < 4; nt++) ldsm2(bf[sl][nt], bb + nt * (8 * PADK * 2));
            }
            #pragma unroll
            for (int mt = 0; mt < 4; mt++)
                #pragma unroll
                for (int nt = 0; nt < 4; nt++) mmah(accH[mt][nt], af[0][mt], bf[0][nt]);
            #pragma unroll
            for (int mt = 0; mt < 4; mt++)
                #pragma unroll
                for (int nt = 0; nt < 4; nt++) mmah(accC[mt][nt], af[0][mt], bf[1][nt]);
            #pragma unroll
            for (int mt = 0; mt < 4; mt++)
                #pragma unroll
                for (int nt = 0; nt < 4; nt++) mmah(accC[mt][nt], af[1][mt], bf[0][nt]);
        }
        __syncthreads();
    }

    #pragma unroll
    for (int mt = 0; mt < 4; mt++) {
        const int row = mBase + warpM + mt * 16 + lr;
        #pragma unroll
        for (int nt = 0; nt < 4; nt++) {
            const int col = nBase + warpN + nt * 8 + 2 * lq;
            const long long o0 = (long long)z * sC + (long long)row * ldc + col;
            const long long o1 = o0 + 8LL * ldc;
            float a[4];
            #pragma unroll
            for (int r = 0; r < 4; r++) a[r] = accH[mt][nt][r] + accC[mt][nt][r];
            if (SPLIT) {
                u16 h[4], m[4];
                #pragma unroll
                for (int r = 0; r < 4; r++) split2(a[r], h[r], m[r]);
                *(u32*)(Ch + o0) = pk(h[0], h[1]); *(u32*)(Ch + o1) = pk(h[2], h[3]);
                *(u32*)(Cm + o0) = pk(m[0], m[1]); *(u32*)(Cm + o1) = pk(m[2], m[3]);
            } else {
                *(float2*)(C + o0) = make_float2(a[0], a[1]);
                *(float2*)(C + o1) = make_float2(a[2], a[3]);
            }
        }
    }
}

__global__ void k_split(const float* __restrict__ in, u16* __restrict__ h,
                        u16* __restrict__ m, int n)
{
    const int i = (blockIdx.x * 256 + threadIdx.x) * 4;
    if (i >= n) return;
    const float4 v = *(const float4*)(in + i);
    u16 hh[4], mm[4];
    split2(v.x, hh[0], mm[0]); split2(v.y, hh[1], mm[1]);
    split2(v.z, hh[2], mm[2]); split2(v.w, hh[3], mm[3]);
    *(uint2*)(h + i) = make_uint2(pk(hh[0], hh[1]), pk(hh[2], hh[3]));
    *(uint2*)(m + i) = make_uint2(pk(mm[0], mm[1]), pk(mm[2], mm[3]));
}

__global__ void k_wtsplit(const float* __restrict__ W, u16* __restrict__ th,
                          u16* __restrict__ tm)
{
    __shared__ float t[32][33];
    const int c0 = blockIdx.x * 32, r0 = blockIdx.y * 32;
    const int tx = threadIdx.x, ty = threadIdx.y;
    #pragma unroll
    for (int k = 0; k < 4; k++)
        t[ty + 8 * k][tx] = W[(long long)(r0 + ty + 8 * k) * DIM + c0 + tx];
    __syncthreads();
    #pragma unroll
    for (int k = 0; k < 4; k++) {
        u16 h, m; split2(t[tx][ty + 8 * k], h, m);
        const long long o = (long long)(c0 + ty + 8 * k) * DIM + r0 + tx;
        th[o] = h; tm[o] = m;
    }
}

// Fused: S rows = G (first) or G @ P_prev^T (sparse); softmax; deterministic sparsify.
__global__ __launch_bounds__(UTH, 1)
void upd_softmax(const float* __restrict__ G,
                 const int* __restrict__ pcnt, const uint2* __restrict__ plst,
                 int* __restrict__ ocnt, uint2* __restrict__ olst, int first)
{
    extern __shared__ float dyn[];
    float* gT0 = dyn;                 // [SEQ][4] rows 0-3 interleaved
    float* gT1 = dyn + SEQ * 4;       // [SEQ][4] rows 4-7 interleaved
    float* s   = dyn + 2 * SEQ * 4;   // [RPB][SEQ]
    __shared__ float wred[16];
    __shared__ float bcast;
    __shared__ int warpcnt[16];
    const int b = blockIdx.y, n0 = blockIdx.x * RPB, tid = threadIdx.x;
    const int wid = tid >> 5, lane = tid & 31;
    const long long gbase = ((long long)b * SEQ + n0) * SEQ;

    if (first) {
        #pragma unroll
        for (int i = 0; i < RPB; i++) {
            const int m4 = tid * 4;
            *(float4*)&s[i * SEQ + m4] = *(const float4*)(G + gbase + (long long)i * SEQ + m4);
        }
        __syncthreads();
    } else {
        #pragma unroll
        for (int i = 0; i < RPB; i++) {
            const int m4 = tid * 4;
            const float4 v = *(const float4*)(G + gbase + (long long)i * SEQ + m4);
            float* dst = (i < 4) ? gT0 : gT1;
            const int ii = i & 3;
            dst[(m4 + 0) * 4 + ii] = v.x;
            dst[(m4 + 1) * 4 + ii] = v.y;
            dst[(m4 + 2) * 4 + ii] = v.z;
            dst[(m4 + 3) * 4 + ii] = v.w;
        }
        __syncthreads();
        #pragma unroll
        for (int t = 0; t < SEQ / UTH; t++) {
            const int m = t * UTH + tid;
            const int row = b * SEQ + m;
            const int c = pcnt[row];
            float a0 = 0, a1 = 0, a2 = 0, a3 = 0, a4 = 0, a5 = 0, a6 = 0, a7 = 0;
            for (int j = 0; j < c; j++) {
                const uint2 u = plst[(long long)j * MTOT + row];   // one coalesced LD.64
                const int jj = u.x;
                const float wj = __uint_as_float(u.y);
                const float4 ga = *(const float4*)&gT0[jj * 4];
                const float4 gb = *(const float4*)&gT1[jj * 4];
                a0 += wj * ga.x; a1 += wj * ga.y; a2 += wj * ga.z; a3 += wj * ga.w;
                a4 += wj * gb.x; a5 += wj * gb.y; a6 += wj * gb.z; a7 += wj * gb.w;
            }
            s[m] = a0; s[SEQ + m] = a1; s[2 * SEQ + m] = a2; s[3 * SEQ + m] = a3;
            s[4 * SEQ + m] = a4; s[5 * SEQ + m] = a5; s[6 * SEQ + m] = a6; s[7 * SEQ + m] = a7;
        }
        __syncthreads();
    }

    for (int i = 0; i < RPB; i++) {
        float* si = s + i * SEQ;
        // max (warp shfl + cross-warp)
        float mx = -INFINITY;
        #pragma unroll
        for (int t = 0; t < SEQ / UTH; t++) mx = fmaxf(mx, si[t * UTH + tid]);
        #pragma unroll
        for (int o = 16; o > 0; o >>= 1) mx = fmaxf(mx, __shfl_xor_sync(0xffffffffu, mx, o));
        if (lane == 0) wred[wid] = mx;
        __syncthreads();
        if (tid == 0) {
            float v = wred[0];
            #pragma unroll
            for (int w2 = 1; w2 < 16; w2++) v = fmaxf(v, wred[w2]);
            bcast = v;
        }
        __syncthreads();
        mx = bcast;
        __syncthreads();
        // sum (cache e back into si)
        float sum = 0.f;
        #pragma unroll
        for (int t = 0; t < SEQ / UTH; t++) {
            const int m = t * UTH + tid;
            const float e = __expf(si[m] - mx);
            si[m] = e;
            sum += e;
        }
        #pragma unroll
        for (int o = 16; o > 0; o >>= 1) sum += __shfl_xor_sync(0xffffffffu, sum, o);
        if (lane == 0) wred[wid] = sum;
        __syncthreads();
        if (tid == 0) {
            float v = 0.f;
            #pragma unroll
            for (int w2 = 0; w2 < 16; w2++) v += wred[w2];
            bcast = v;
        }
        __syncthreads();
        const float tot = bcast;
        const float inv = 1.0f / tot, thr = tot * 1e-10f;
        __syncthreads();
        // deterministic ordered emission (ascending m via ballot + block scan)
        const long long orow = (long long)(b * SEQ + n0 + i);
        int base = 0;
        #pragma unroll
        for (int t = 0; t < SEQ / UTH; t++) {
            const int m = t * UTH + tid;
            const float e = si[m];
            const bool p = (e > thr);
            const unsigned mask = __ballot_sync(0xffffffffu, p);
            if (lane == 0) warpcnt[wid] = __popc(mask);
            const int myoff = __popc(mask & ((1u << lane) - 1u));
            __syncthreads();
            int pre = 0, tt = 0;
            #pragma unroll
            for (int w2 = 0; w2 < 16; w2++) {
                const int cc = warpcnt[w2];
                if (w2 < wid) pre += cc;
                tt += cc;
            }
            const int off = base + pre + myoff;
            if (p && off < MAXNZ)
                olst[(long long)off * MTOT + orow] = make_uint2((u32)m, __float_as_uint(e * inv));
            base += tt;
            __syncthreads();
        }
        if (tid == 0) ocnt[orow] = min(base, MAXNZ);
        __syncthreads();
    }
}

// y[n,:] = sum_j w[n,j] * x[b, idx[n,j], :]
__global__ void sparse_av(const int* __restrict__ cnt, const uint2* __restrict__ lst,
                          const float* __restrict__ x, float* __restrict__ y)
{
    __shared__ uint2 sl[MAXNZ];
    const int n = blockIdx.x, b = n >> 11, tid = threadIdx.x;
    const int c = cnt[n];
    for (int j = tid; j < c; j += 256) sl[j] = lst[(long long)j * MTOT + n];
    __syncthreads();
    const float* xb = x + (long long)b * SEQ * DIM;
    float4 acc = make_float4(0.f, 0.f, 0.f, 0.f);
    const int d0 = tid * 4;
    for (int j = 0; j < c; j++) {
        const float wj = __uint_as_float(sl[j].y);
        const float4 xv = *(const float4*)(xb + (long long)sl[j].x * DIM + d0);
        acc.x += wj * xv.x; acc.y += wj * xv.y;
        acc.z += wj * xv.z; acc.w += wj * xv.w;
    }
    *(float4*)(y + (long long)n * DIM + d0) = acc;
}

#define GETP(name, sym) u16* name; cudaGetSymbolAddress((void**)&name, sym)

extern "C" void kernel_launch(void* const* d_in, const int* in_sizes, int n_in,
                              void* d_out, int out_size)
{
    const float* x  = (const float*)d_in[0];
    const float* WQ = (const float*)d_in[1];
    const float* WK = (const float*)d_in[2];

    GETP(xh, g_xh);     GETP(xm, g_xm);
    GETP(WQTh, g_WQTh); GETP(WQTm, g_WQTm);
    GETP(WKTh, g_WKTh); GETP(WKTm, g_WKTm);
    GETP(W2Th, g_W2Th); GETP(W2Tm, g_W2Tm);
    GETP(KWh, g_KWh);   GETP(KWm, g_KWm);
    float* G; cudaGetSymbolAddress((void**)&G, g_G);
    int* cnt; cudaGetSymbolAddress((void**)&cnt, g_cnt);
    uint2* lst; cudaGetSymbolAddress((void**)&lst, g_lst);
    int* cntA = cnt, *cntB = cnt + MTOT;
    uint2* lstA = lst, *lstB = lst + (long long)MTOT * MAXNZ;

    cudaFuncSetAttribute(gemm_h2<0>, cudaFuncAttributeMaxDynamicSharedMemorySize, SMEMTOT);
    cudaFuncSetAttribute(gemm_h2<1>, cudaFuncAttributeMaxDynamicSharedMemorySize, SMEMTOT);
    cudaFuncSetAttribute(upd_softmax, cudaFuncAttributeMaxDynamicSharedMemorySize, UPD_SMEM);

    k_split<<<MTOT * DIM / 1024, 256>>>(x, xh, xm, MTOT * DIM);
    k_wtsplit<<<dim3(DIM / 32, DIM / 32), dim3(32, 8)>>>(WQ, WQTh, WQTm);
    k_wtsplit<<<dim3(DIM / 32, DIM / 32), dim3(32, 8)>>>(WK, WKTh, WKTm);

    // W2T[e,d] = sum_j WQ[j,e]*WK[j,d]
    gemm_h2<1><<<dim3(DIM / 128, DIM / 128, 1), 256, SMEMTOT>>>(
        WQTh, WQTm, WKTh, WKTm, nullptr, W2Th, W2Tm, DIM, DIM, 0, 0, 0);
    // KW[n,e] = sum_d x[n,d]*W2T[e,d]
    gemm_h2<1><<<dim3(DIM / 128, MTOT / 128, 1), 256, SMEMTOT>>>(
        xh, xm, W2Th, W2Tm, nullptr, KWh, KWm, DIM, DIM, 0, 0, 0);
    // G[b,n,j] = sum_d KW[b,n,d]*x[b,j,d]
    gemm_h2<0><<<dim3(SEQ / 128, SEQ / 128, BATCH), 256, SMEMTOT>>>(
        KWh, KWm, xh, xm, G, nullptr, nullptr, DIM, SEQ,
        (long long)SEQ * DIM, (long long)SEQ * DIM, (long long)SEQ * SEQ);

    // iter 1: P1 = softmax(G)
    upd_softmax<<<dim3(SEQ / RPB, BATCH), UTH, UPD_SMEM>>>(
        G, nullptr, nullptr, cntA, lstA, 1);
    // iters 2..5: S_t = G @ P^T, softmax, sparsify  (ping-pong)
    for (int it = 1; it < NITER; ++it) {
        upd_softmax<<<dim3(SEQ / RPB, BATCH), UTH, UPD_SMEM>>>(
            G, cntA, lstA, cntB, lstB, 0);
        int* tc = cntA; cntA = cntB; cntB = tc;
        uint2* tl = lstA; lstA = lstB; lstB = tl;
    }
    // y = P5 @ x
    sparse_av<<<MTOT, 256>>>(cntA, lstA, x, (float*)d_out);
}

// round 16
// speedup vs baseline: 1.1505x; 1.1505x over previous
#include <cuda_runtime.h>
#include <cuda_fp16.h>
#include <stdint.h>
#include <math.h>

#define BATCH 4
#define SEQ 2048
#define DIM 1024
#define MTOT (BATCH*SEQ)
#define NITER 5
#define PADK 40
#define ARRB (128*PADK*2)
#define STGB (4*ARRB)
#define SMEMTOT (3*STGB)
#define MAXNZ 256
#define RPB 4
#define UPD_SMEM (2 * RPB * SEQ * 4)   // gT (32KB) + s (32KB)

typedef uint16_t u16;
typedef uint32_t u32;

__device__ u16 g_xh[MTOT*DIM], g_xm[MTOT*DIM];
__device__ u16 g_WQTh[DIM*DIM], g_WQTm[DIM*DIM];
__device__ u16 g_WKTh[DIM*DIM], g_WKTm[DIM*DIM];
__device__ u16 g_W2Th[DIM*DIM], g_W2Tm[DIM*DIM];
__device__ u16 g_KWh[MTOT*DIM], g_KWm[MTOT*DIM];
__device__ float g_G[BATCH*SEQ*SEQ];
__device__ int   g_cnt[2][MTOT];
__device__ uint2 g_lst[2][MTOT*MAXNZ];   // entry-major: [p*MTOT+row] = {idx, w bits}

__device__ __forceinline__ u32 smem_u32(const void* p) {
    u32 a;
    asm("{ .reg .u64 t; cvta.to.shared.u64 t, %1; cvt.u32.u64 %0, t; }" : "=r"(a) : "l"(p));
    return a;
}
__device__ __forceinline__ void cpa16(u32 s, const void* g) {
    asm volatile("cp.async.cg.shared.global [%0], [%1], 16;" :: "r"(s), "l"(g) : "memory");
}
__device__ __forceinline__ void mmah(float* c, const u32* a, const u32* b) {
    asm volatile("mma.sync.aligned.m16n8k16.row.col.f32.f16.f16.f32 "
        "{%0,%1,%2,%3}, {%4,%5,%6,%7}, {%8,%9}, {%0,%1,%2,%3};"
        : "+f"(c[0]), "+f"(c[1]), "+f"(c[2]), "+f"(c[3])
        : "r"(a[0]), "r"(a[1]), "r"(a[2]), "r"(a[3]), "r"(b[0]), "r"(b[1]));
}
__device__ __forceinline__ void ldsm4(u32* r, u32 a) {
    asm volatile("ldmatrix.sync.aligned.m8n8.x4.shared.b16 {%0,%1,%2,%3}, [%4];"
        : "=r"(r[0]), "=r"(r[1]), "=r"(r[2]), "=r"(r[3]) : "r"(a));
}
__device__ __forceinline__ void ldsm2(u32* r, u32 a) {
    asm volatile("ldmatrix.sync.aligned.m8n8.x2.shared.b16 {%0,%1}, [%2];"
        : "=r"(r[0]), "=r"(r[1]) : "r"(a));
}
__device__ __forceinline__ void split2(float v, u16& h, u16& m) {
    __half hh = __float2half_rn(v);
    float r = v - __half2float(hh);
    __half mm = __float2half_rn(r);
    h = __half_as_ushort(hh); m = __half_as_ushort(mm);
}
__device__ __forceinline__ u32 pk(u16 a, u16 b) { return (u32)a | ((u32)b << 16); }

// C[M,N] = A[M,K]*B[N,K]^T, fp16 2-term, 3 passes, dual accumulators.
template <int SPLIT>
__global__ __launch_bounds__(256, 1)
void gemm_h2(const u16* __restrict__ Ah, const u16* __restrict__ Am,
             const u16* __restrict__ Bh, const u16* __restrict__ Bm,
             float* __restrict__ C, u16* __restrict__ Ch, u16* __restrict__ Cm,
             int Ktot, int ldc, long long sA, long long sB, long long sC)
{
    extern __shared__ char smc[];
    const u32 sb = smem_u32(smc);
    const int tid = threadIdx.x, wid = tid >> 5, lane = tid & 31;
    const int lr = lane >> 2, lq = lane & 3;
    const int mBase = blockIdx.y * 128, nBase = blockIdx.x * 128, z = blockIdx.z;
    const int warpM = (wid >> 2) * 64, warpN = (wid & 3) * 32;
    const int nst = Ktot >> 5;
    const long long aOff = (long long)z * sA, bOff = (long long)z * sB;

    const int l15 = lane & 15;
    const u32 aoff = ((u32)(warpM + l15) * PADK + (lane >> 4) * 8) * 2;
    const u32 boff = ((u32)(warpN + (l15 & 7)) * PADK + ((l15 >> 3) & 1) * 8) * 2;

    float accH[4][4][4], accC[4][4][4];
    #pragma unroll
    for (int i = 0; i < 4; i++)
        #pragma unroll
        for (int j = 0; j < 4; j++)
            #pragma unroll
            for (int r = 0; r < 4; r++) { accH[i][j][r] = 0.f; accC[i][j][r] = 0.f; }

    const u16* gp[4] = {Ah, Am, Bh, Bm};

    auto load_stage = [&](int s) {
        const u32 st = sb + (s % 3) * STGB;
        const int k0 = s << 5;
        #pragma unroll
        for (int a = 0; a < 4; a++) {
            const long long ro = (a < 2) ? aOff : bOff;
            const int rb = (a < 2) ? mBase : nBase;
            #pragma unroll
            for (int i = 0; i < 2; i++) {
                const int u = i * 256 + tid;
                const int r = u >> 2, kc = (u & 3) * 8;
                cpa16(st + a * ARRB + (r * PADK + kc) * 2,
                      gp[a] + ro + (long long)(rb + r) * Ktot + k0 + kc);
            }
        }
        asm volatile("cp.async.commit_group;" ::: "memory");
    };

    load_stage(0);
    if (nst > 1) load_stage(1);

    for (int s = 0; s < nst; s++) {
        asm volatile("cp.async.wait_group 1;" ::: "memory");
        __syncthreads();
        if (s + 2 < nst) load_stage(s + 2);

        const u32 stB = sb + (s % 3) * STGB;

        #pragma unroll
        for (int kk = 0; kk < 2; kk++) {
            u32 af[2][4][4], bf[2][4][2];
            #pragma unroll
            for (int sl = 0; sl < 2; sl++) {
                const u32 ab = stB + sl * ARRB + aoff + kk * 32;
                const u32 bb = stB + (2 + sl) * ARRB + boff + kk * 32;
                #pragma unroll
                for (int mt = 0; mt < 4; mt++) ldsm4(af[sl][mt], ab + mt * (16 * PADK * 2));
                #pragma unroll
                for (int nt = 0; nt < 4; nt++) ldsm2(bf[sl][nt], bb + nt * (8 * PADK * 2));
            }
            #pragma unroll
            for (int mt = 0; mt < 4; mt++)
                #pragma unroll
                for (int nt = 0; nt < 4; nt++) mmah(accH[mt][nt], af[0][mt], bf[0][nt]);
            #pragma unroll
            for (int mt = 0; mt < 4; mt++)
                #pragma unroll
                for (int nt = 0; nt < 4; nt++) mmah(accC[mt][nt], af[0][mt], bf[1][nt]);
            #pragma unroll
            for (int mt = 0; mt < 4; mt++)
                #pragma unroll
                for (int nt = 0; nt < 4; nt++) mmah(accC[mt][nt], af[1][mt], bf[0][nt]);
        }
        __syncthreads();
    }

    #pragma unroll
    for (int mt = 0; mt < 4; mt++) {
        const int row = mBase + warpM + mt * 16 + lr;
        #pragma unroll
        for (int nt = 0; nt < 4; nt++) {
            const int col = nBase + warpN + nt * 8 + 2 * lq;
            const long long o0 = (long long)z * sC + (long long)row * ldc + col;
            const long long o1 = o0 + 8LL * ldc;
            float a[4];
            #pragma unroll
            for (int r = 0; r < 4; r++) a[r] = accH[mt][nt][r] + accC[mt][nt][r];
            if (SPLIT) {
                u16 h[4], m[4];
                #pragma unroll
                for (int r = 0; r < 4; r++) split2(a[r], h[r], m[r]);
                *(u32*)(Ch + o0) = pk(h[0], h[1]); *(u32*)(Ch + o1) = pk(h[2], h[3]);
                *(u32*)(Cm + o0) = pk(m[0], m[1]); *(u32*)(Cm + o1) = pk(m[2], m[3]);
            } else {
                *(float2*)(C + o0) = make_float2(a[0], a[1]);
                *(float2*)(C + o1) = make_float2(a[2], a[3]);
            }
        }
    }
}

__global__ void k_split(const float* __restrict__ in, u16* __restrict__ h,
                        u16* __restrict__ m, int n)
{
    const int i = (blockIdx.x * 256 + threadIdx.x) * 4;
    if (i >= n) return;
    const float4 v = *(const float4*)(in + i);
    u16 hh[4], mm[4];
    split2(v.x, hh[0], mm[0]); split2(v.y, hh[1], mm[1]);
    split2(v.z, hh[2], mm[2]); split2(v.w, hh[3], mm[3]);
    *(uint2*)(h + i) = make_uint2(pk(hh[0], hh[1]), pk(hh[2], hh[3]));
    *(uint2*)(m + i) = make_uint2(pk(mm[0], mm[1]), pk(mm[2], mm[3]));
}

__global__ void k_wtsplit(const float* __restrict__ W, u16* __restrict__ th,
                          u16* __restrict__ tm)
{
    __shared__ float t[32][33];
    const int c0 = blockIdx.x * 32, r0 = blockIdx.y * 32;
    const int tx = threadIdx.x, ty = threadIdx.y;
    #pragma unroll
    for (int k = 0; k < 4; k++)
        t[ty + 8 * k][tx] = W[(long long)(r0 + ty + 8 * k) * DIM + c0 + tx];
    __syncthreads();
    #pragma unroll
    for (int k = 0; k < 4; k++) {
        u16 h, m; split2(t[tx][ty + 8 * k], h, m);
        const long long o = (long long)(c0 + ty + 8 * k) * DIM + r0 + tx;
        th[o] = h; tm[o] = m;
    }
}

// Fused: S rows = G (first) or G @ P_prev^T (sparse); softmax; sparsify.
// R13 structure (RPB=4, 256thr, occ 2) + packed uint2 lists + cached exp.
__global__ __launch_bounds__(256, 2)
void upd_softmax(const float* __restrict__ G,
                 const int* __restrict__ pcnt, const uint2* __restrict__ plst,
                 int* __restrict__ ocnt, uint2* __restrict__ olst, int first)
{
    extern __shared__ float dyn[];
    float* gT = dyn;                // [SEQ][RPB] interleaved
    float* s  = dyn + RPB * SEQ;    // [RPB][SEQ]
    __shared__ float red[256];
    __shared__ int ctr;
    const int b = blockIdx.y, n0 = blockIdx.x * RPB, tid = threadIdx.x;
    const long long gbase = ((long long)b * SEQ + n0) * SEQ;

    if (first) {
        #pragma unroll
        for (int i = 0; i < RPB; i++)
            for (int m4 = tid * 4; m4 < SEQ; m4 += 1024)
                *(float4*)&s[i * SEQ + m4] = *(const float4*)(G + gbase + (long long)i * SEQ + m4);
        __syncthreads();
    } else {
        #pragma unroll
        for (int i = 0; i < RPB; i++)
            for (int m4 = tid * 4; m4 < SEQ; m4 += 1024) {
                const float4 v = *(const float4*)(G + gbase + (long long)i * SEQ + m4);
                gT[(m4 + 0) * RPB + i] = v.x;
                gT[(m4 + 1) * RPB + i] = v.y;
                gT[(m4 + 2) * RPB + i] = v.z;
                gT[(m4 + 3) * RPB + i] = v.w;
            }
        __syncthreads();
        for (int m = tid; m < SEQ; m += 256) {
            const int row = b * SEQ + m;
            const int c = pcnt[row];
            float a0 = 0, a1 = 0, a2 = 0, a3 = 0;
            for (int j = 0; j < c; j++) {
                const uint2 u = plst[(long long)j * MTOT + row];  // one coalesced LD.64
                const float wj = __uint_as_float(u.y);
                const float4 gv = *(const float4*)&gT[u.x * RPB]; // one LDS.128
                a0 += wj * gv.x; a1 += wj * gv.y;
                a2 += wj * gv.z; a3 += wj * gv.w;
            }
            s[m] = a0; s[SEQ + m] = a1; s[2 * SEQ + m] = a2; s[3 * SEQ + m] = a3;
        }
        __syncthreads();
    }

    for (int i = 0; i < RPB; i++) {
        float* si = s + i * SEQ;
        float mx = -INFINITY;
        for (int m = tid; m < SEQ; m += 256) mx = fmaxf(mx, si[m]);
        red[tid] = mx; __syncthreads();
        #pragma unroll
        for (int st = 128; st > 0; st >>= 1) {
            if (tid < st) red[tid] = fmaxf(red[tid], red[tid + st]);
            __syncthreads();
        }
        mx = red[0]; __syncthreads();
        float sum = 0.f;
        for (int m = tid; m < SEQ; m += 256) {
            const float e = __expf(si[m] - mx);
            si[m] = e;                          // cache e for emission pass
            sum += e;
        }
        red[tid] = sum; __syncthreads();
        #pragma unroll
        for (int st = 128; st > 0; st >>= 1) {
            if (tid < st) red[tid] += red[tid + st];
            __syncthreads();
        }
        const float tot = red[0];
        const float inv = 1.0f / tot, thr = tot * 1e-10f;
        if (tid == 0) ctr = 0;
        __syncthreads();
        const long long orow = (long long)(b * SEQ + n0 + i);
        for (int m = tid; m < SEQ; m += 256) {
            const float e = si[m];
            if (e > thr) {
                const int p = atomicAdd(&ctr, 1);
                if (p < MAXNZ)
                    olst[(long long)p * MTOT + orow] =
                        make_uint2((u32)m, __float_as_uint(e * inv));
            }
        }
        __syncthreads();
        if (tid == 0) ocnt[orow] = min(ctr, MAXNZ);
        __syncthreads();
    }
}

// y[n,:] = sum_j w[n,j] * x[b, idx[n,j], :]
__global__ void sparse_av(const int* __restrict__ cnt, const uint2* __restrict__ lst,
                          const float* __restrict__ x, float* __restrict__ y)
{
    __shared__ uint2 sl[MAXNZ];
    const int n = blockIdx.x, b = n >> 11, tid = threadIdx.x;
    const int c = cnt[n];
    for (int j = tid; j < c; j += 256) sl[j] = lst[(long long)j * MTOT + n];
    __syncthreads();
    const float* xb = x + (long long)b * SEQ * DIM;
    float4 acc = make_float4(0.f, 0.f, 0.f, 0.f);
    const int d0 = tid * 4;
    for (int j = 0; j < c; j++) {
        const float wj = __uint_as_float(sl[j].y);
        const float4 xv = *(const float4*)(xb + (long long)sl[j].x * DIM + d0);
        acc.x += wj * xv.x; acc.y += wj * xv.y;
        acc.z += wj * xv.z; acc.w += wj * xv.w;
    }
    *(float4*)(y + (long long)n * DIM + d0) = acc;
}

#define GETP(name, sym) u16* name; cudaGetSymbolAddress((void**)&name, sym)

extern "C" void kernel_launch(void* const* d_in, const int* in_sizes, int n_in,
                              void* d_out, int out_size)
{
    const float* x  = (const float*)d_in[0];
    const float* WQ = (const float*)d_in[1];
    const float* WK = (const float*)d_in[2];

    GETP(xh, g_xh);     GETP(xm, g_xm);
    GETP(WQTh, g_WQTh); GETP(WQTm, g_WQTm);
    GETP(WKTh, g_WKTh); GETP(WKTm, g_WKTm);
    GETP(W2Th, g_W2Th); GETP(W2Tm, g_W2Tm);
    GETP(KWh, g_KWh);   GETP(KWm, g_KWm);
    float* G; cudaGetSymbolAddress((void**)&G, g_G);
    int* cnt; cudaGetSymbolAddress((void**)&cnt, g_cnt);
    uint2* lst; cudaGetSymbolAddress((void**)&lst, g_lst);
    int* cntA = cnt, *cntB = cnt + MTOT;
    uint2* lstA = lst, *lstB = lst + (long long)MTOT * MAXNZ;

    cudaFuncSetAttribute(gemm_h2<0>, cudaFuncAttributeMaxDynamicSharedMemorySize, SMEMTOT);
    cudaFuncSetAttribute(gemm_h2<1>, cudaFuncAttributeMaxDynamicSharedMemorySize, SMEMTOT);
    cudaFuncSetAttribute(upd_softmax, cudaFuncAttributeMaxDynamicSharedMemorySize, UPD_SMEM);

    k_split<<<MTOT * DIM / 1024, 256>>>(x, xh, xm, MTOT * DIM);
    k_wtsplit<<<dim3(DIM / 32, DIM / 32), dim3(32, 8)>>>(WQ, WQTh, WQTm);
    k_wtsplit<<<dim3(DIM / 32, DIM / 32), dim3(32, 8)>>>(WK, WKTh, WKTm);

    // W2T[e,d] = sum_j WQ[j,e]*WK[j,d]
    gemm_h2<1><<<dim3(DIM / 128, DIM / 128, 1), 256, SMEMTOT>>>(
        WQTh, WQTm, WKTh, WKTm, nullptr, W2Th, W2Tm, DIM, DIM, 0, 0, 0);
    // KW[n,e] = sum_d x[n,d]*W2T[e,d]
    gemm_h2<1><<<dim3(DIM / 128, MTOT / 128, 1), 256, SMEMTOT>>>(
        xh, xm, W2Th, W2Tm, nullptr, KWh, KWm, DIM, DIM, 0, 0, 0);
    // G[b,n,j] = sum_d KW[b,n,d]*x[b,j,d]
    gemm_h2<0><<<dim3(SEQ / 128, SEQ / 128, BATCH), 256, SMEMTOT>>>(
        KWh, KWm, xh, xm, G, nullptr, nullptr, DIM, SEQ,
        (long long)SEQ * DIM, (long long)SEQ * DIM, (long long)SEQ * SEQ);

    // iter 1: P1 = softmax(G)
    upd_softmax<<<dim3(SEQ / RPB, BATCH), 256, UPD_SMEM>>>(
        G, nullptr, nullptr, cntA, lstA, 1);
    // iters 2..5: S_t = G @ P^T, softmax, sparsify  (ping-pong)
    for (int it = 1; it < NITER; ++it) {
        upd_softmax<<<dim3(SEQ / RPB, BATCH), 256, UPD_SMEM>>>(
            G, cntA, lstA, cntB, lstB, 0);
        int* tc = cntA; cntA = cntB; cntB = tc;
        uint2* tl = lstA; lstA = lstB; lstB = tl;
    }
    // y = P5 @ x
    sparse_av<<<MTOT, 256>>>(cntA, lstA, x, (float*)d_out);
}